// round 8
// baseline (speedup 1.0000x reference)
#include <cuda_runtime.h>
#include <cstdint>

#define BSZ 512
#define TSZ 512
#define FF  64
#define UU  512
#define PP  32
#define K1P 640                 // 512 hs | 64 x | 32 acc | 32 zero-pad
#define NCTA 128
#define NTHR 512
#define KC   16
#define NSPL 8                  // split-K factor

// ---------------- device-global scratch ----------------
__device__ float g_W0[K1P * UU];       // [640,512] rows: WA0 | WB0(x) | WB0(acc) | 0
__device__ float g_W1[2 * UU * UU];    // rows 0-511 WA1, 512-1023 E1=WC0@WBr0
__device__ float g_W2[2 * UU * UU];    // rows 0-511 WA2, 512-1023 E2=WC1@WBr1
__device__ float g_Wo[UU * PP];        // Eo = WC2@Wout
__device__ float g_c0[UU], g_c1[UU], g_c2[UU], g_co[PP];
__device__ float g_NS[3][NSPL][BSZ * UU];  // split-K partials per layer
__device__ float g_HM[3][BSZ * UU];        // merged states (= hs for next step)
__device__ float g_ACC[BSZ * PP];
__device__ unsigned g_bar;

// ---------------- FFMA2 helpers ----------------
__device__ __forceinline__ void fma2(unsigned long long& d, unsigned long long a,
                                     unsigned long long b) {
    asm("fma.rn.f32x2 %0, %1, %2, %0;" : "+l"(d) : "l"(a), "l"(b));
}
__device__ __forceinline__ void unpack2(unsigned long long v, float& lo, float& hi) {
    asm("mov.b64 {%0, %1}, %2;" : "=f"(lo), "=f"(hi) : "l"(v));
}

// ---------------- grid barrier (128 CTAs, single wave) ----------------
__device__ __forceinline__ void gsync(unsigned& barn) {
    barn += 1;
    const unsigned target = barn * NCTA;
    __syncthreads();
    if (threadIdx.x == 0) {
        asm volatile("red.release.gpu.global.add.u32 [%0], 1;"
                     :: "l"(&g_bar) : "memory");
        unsigned v;
        do {
            asm volatile("ld.acquire.gpu.u32 %0, [%1];" : "=r"(v) : "l"(&g_bar) : "memory");
        } while (v < target);
    }
    __syncthreads();
}

// ---------------- A-operand fetch (merged across split-K partials) ----------
__device__ __forceinline__ float4 loadA(int phase, int b, int k, int t,
                                        const float* __restrict__ x, bool wb) {
    float4 v;
    if (phase == 1) {
        if (k < UU)
            v = __ldcg((const float4*)&g_HM[0][b * UU + k]);
        else if (k < UU + FF)
            v = __ldg((const float4*)&x[((size_t)b * TSZ + t) * FF + (k - UU)]);
        else if (k < UU + FF + PP)
            v = __ldcg((const float4*)&g_ACC[b * PP + (k - UU - FF)]);
        else
            v = make_float4(0.f, 0.f, 0.f, 0.f);
    } else {
        if (k < UU) {
            v = __ldcg((const float4*)&g_HM[phase - 1][b * UU + k]);
        } else {
            const int off = b * UU + (k - UU);
            const float(*P)[BSZ * UU] = g_NS[phase - 2];
            v = __ldcg((const float4*)&P[0][off]);
#pragma unroll
            for (int s = 1; s < NSPL; s++) {
                const float4 w = __ldcg((const float4*)&P[s][off]);
                v.x += w.x; v.y += w.y; v.z += w.z; v.w += w.w;
            }
            if (wb) *(float4*)&g_HM[phase - 2][off] = v;  // piggyback merge
        }
    }
    return v;
}

// ---------------- main GEMM phase: CTA tile 128x128, warp tile 32x32 --------
// smem: As [2][KC][256] dup pairs (8192 f) + Bs [2][KC][128] (4096 f) = 48KB
__device__ void phase_gemm(float* sm, int phase, int t, const float* __restrict__ x,
                           const float* __restrict__ W, const float* __restrict__ cb,
                           int Ktot, float* __restrict__ dst_base) {
    const int tid = threadIdx.x;
    const int cta = blockIdx.x;
    const int s   = cta & 7;
    const int nt  = (cta >> 3) & 3;
    const int mt  = cta >> 5;
    const int b0 = mt * 128, n0 = nt * 128;
    const int kslice = Ktot / NSPL;       // 80 (P1) or 128 (P2/P3)
    const int kbase0 = s * kslice;
    const int ntiles = kslice / KC;       // 5 or 8
    float* __restrict__ dst = dst_base + (size_t)s * BSZ * UU;
    const bool wb = (phase >= 2) && (nt == 0);

    // fill indices: A one float4/thread (row, k-quad), B one float4/thread
    const int fr = tid & 127, fq = tid >> 7;   // A: row 0..127, quad 0..3
    const int bk = tid >> 5,  bc = tid & 31;   // B: kk 0..15, col-quad 0..31

    // compute indices: 16 warps in 4x4 grid of 32x32 warp tiles
    const int wid = tid >> 5, lane = tid & 31;
    const int wr = wid >> 2, wn = wid & 3;
    const int lr = lane & 3, lc = lane >> 2;
    const int row0 = wr * 32 + lr * 8;         // 8 rows per thread
    const int col0 = wn * 32 + lc * 4;         // 4 cols per thread

    float* As = sm;                    // dup-pair A: [buf][kk][2*row]
    float* Bs = sm + 2 * KC * 256;     // [buf][kk][col]

    unsigned long long acc[8][2];
#pragma unroll
    for (int i = 0; i < 8; i++) { acc[i][0] = 0ULL; acc[i][1] = 0ULL; }

    // prefetch tile 0
    float4 ra = loadA(phase, b0 + fr, kbase0 + 4 * fq, t, x, wb);
    float4 rb = __ldg((const float4*)&W[(size_t)(kbase0 + bk) * UU + n0 + 4 * bc]);
    {
        float* a = As + 2 * fr;
        *(float2*)(a + (4 * fq + 0) * 256) = make_float2(ra.x, ra.x);
        *(float2*)(a + (4 * fq + 1) * 256) = make_float2(ra.y, ra.y);
        *(float2*)(a + (4 * fq + 2) * 256) = make_float2(ra.z, ra.z);
        *(float2*)(a + (4 * fq + 3) * 256) = make_float2(ra.w, ra.w);
        *(float4*)(Bs + bk * 128 + 4 * bc) = rb;
    }
    __syncthreads();

    int buf = 0;
    for (int it = 0; it < ntiles; it++) {
        const bool more = (it + 1 < ntiles);
        if (more) {
            const int kb = kbase0 + (it + 1) * KC;
            ra = loadA(phase, b0 + fr, kb + 4 * fq, t, x, wb);
            rb = __ldg((const float4*)&W[(size_t)(kb + bk) * UU + n0 + 4 * bc]);
        }
        const float* ab = As + buf * (KC * 256) + 2 * row0;   // 4-addr broadcast
        const float* bb = Bs + buf * (KC * 128) + col0;       // 128B span
#pragma unroll
        for (int kk = 0; kk < KC; kk++) {
            const ulonglong2 b2 = *(const ulonglong2*)(bb + kk * 128);
#pragma unroll
            for (int i = 0; i < 4; i++) {
                const ulonglong2 a2 = *(const ulonglong2*)(ab + kk * 256 + 4 * i);
                fma2(acc[2 * i + 0][0], a2.x, b2.x);
                fma2(acc[2 * i + 0][1], a2.x, b2.y);
                fma2(acc[2 * i + 1][0], a2.y, b2.x);
                fma2(acc[2 * i + 1][1], a2.y, b2.y);
            }
        }
        if (more) {
            const int nb = buf ^ 1;
            float* a = As + nb * (KC * 256) + 2 * fr;
            *(float2*)(a + (4 * fq + 0) * 256) = make_float2(ra.x, ra.x);
            *(float2*)(a + (4 * fq + 1) * 256) = make_float2(ra.y, ra.y);
            *(float2*)(a + (4 * fq + 2) * 256) = make_float2(ra.z, ra.z);
            *(float2*)(a + (4 * fq + 3) * 256) = make_float2(ra.w, ra.w);
            *(float4*)(Bs + nb * (KC * 128) + bk * 128 + 4 * bc) = rb;
        }
        __syncthreads();
        buf ^= 1;
    }

    // epilogue: bias only on partial s==0
    float4 bias = make_float4(0.f, 0.f, 0.f, 0.f);
    if (s == 0) bias = __ldg((const float4*)&cb[n0 + col0]);
#pragma unroll
    for (int r = 0; r < 8; r++) {
        float x0, x1, x2, x3;
        unpack2(acc[r][0], x0, x1);
        unpack2(acc[r][1], x2, x3);
        *(float4*)&dst[(size_t)(b0 + row0 + r) * UU + n0 + col0] =
            make_float4(x0 + bias.x, x1 + bias.y, x2 + bias.z, x3 + bias.w);
    }
}

// ---------------- phase 4: merge ns2, res = ns2@Eo + co, acc += res ---------
__device__ void phase4(float* sm, int t, float* __restrict__ out) {
    const int tid = threadIdx.x;
    const int b0 = blockIdx.x * 4;       // 4 batch rows per CTA
    float* Hs = sm;                       // 2048 floats, aliases GEMM smem
    {
        const int off = b0 * UU + tid * 4;      // 512 threads x float4 = 2048 f
        float4 v = __ldcg((const float4*)&g_NS[2][0][off]);
#pragma unroll
        for (int s = 1; s < NSPL; s++) {
            const float4 w = __ldcg((const float4*)&g_NS[2][s][off]);
            v.x += w.x; v.y += w.y; v.z += w.z; v.w += w.w;
        }
        *(float4*)&g_HM[2][off] = v;     // piggyback merge -> hs2 for next step
        *(float4*)&Hs[tid * 4] = v;
    }
    __syncthreads();
    if (tid < 128) {
        const int r = tid >> 5, c = tid & 31;
        const float* h = Hs + r * UU;    // warp-uniform (broadcast)
        float s0 = 0.f, s1 = 0.f, s2 = 0.f, s3 = 0.f;
#pragma unroll 4
        for (int k = 0; k < UU; k += 4) {
            s0 = fmaf(h[k + 0], __ldg(&g_Wo[(k + 0) * PP + c]), s0);
            s1 = fmaf(h[k + 1], __ldg(&g_Wo[(k + 1) * PP + c]), s1);
            s2 = fmaf(h[k + 2], __ldg(&g_Wo[(k + 2) * PP + c]), s2);
            s3 = fmaf(h[k + 3], __ldg(&g_Wo[(k + 3) * PP + c]), s3);
        }
        const float res = (s0 + s1) + (s2 + s3) + __ldg(&g_co[c]);
        const int b = b0 + r;
        g_ACC[b * PP + c] = __ldcg(&g_ACC[b * PP + c]) + res;
        out[((size_t)b * TSZ + t) * PP + c] = res;
    }
    __syncthreads();
}

// ---------------- persistent time loop over a segment [t0,t1) --------------
__global__ void __launch_bounds__(NTHR, 1)
rnn_run(const float* __restrict__ x, float* __restrict__ out, int t0, int t1) {
    __shared__ float sm[12288];          // exactly 48 KB
    unsigned barn = (unsigned)t0 * 4;    // barrier epoch continues across segments
    for (int t = t0; t < t1; t++) {
        phase_gemm(sm, 1, t, x, g_W0, g_c0, K1P,    &g_NS[0][0][0]);
        gsync(barn);
        phase_gemm(sm, 2, t, x, g_W1, g_c1, 2 * UU, &g_NS[1][0][0]);
        gsync(barn);
        phase_gemm(sm, 3, t, x, g_W2, g_c2, 2 * UU, &g_NS[2][0][0]);
        gsync(barn);
        phase4(sm, t, out);
        gsync(barn);
    }
}

// ---------------- setup ----------------
__global__ void pack_init(const float* __restrict__ WA, const float* __restrict__ WB0) {
    const size_t tid = (size_t)blockIdx.x * blockDim.x + threadIdx.x;
    const size_t stride = (size_t)gridDim.x * blockDim.x;
    for (size_t i = tid; i < (size_t)K1P * UU; i += stride) {
        const int k = (int)(i >> 9), n = (int)(i & 511);
        float v;
        if (k < UU) v = WA[(size_t)k * UU + n];
        else if (k < UU + FF + PP) v = WB0[(size_t)(k - UU) * UU + n];
        else v = 0.f;
        g_W0[i] = v;
    }
    for (size_t i = tid; i < (size_t)UU * UU; i += stride) {
        g_W1[i] = WA[(size_t)UU * UU + i];
        g_W2[i] = WA[(size_t)2 * UU * UU + i];
    }
    for (size_t i = tid; i < (size_t)3 * BSZ * UU; i += stride) (&g_HM[0][0])[i] = 0.f;
    for (size_t i = tid; i < (size_t)BSZ * PP; i += stride) g_ACC[i] = 0.f;
    if (tid == 0) g_bar = 0u;
}

// fused: z=0 -> E1 into g_W1[512:], z=1 -> E2 into g_W2[512:], z=2 -> Eo into g_Wo
__global__ void gemm_pre_all(const float* __restrict__ WC, const float* __restrict__ WBr,
                             const float* __restrict__ Wout) {
    const int which = blockIdx.z;
    if (which == 2 && blockIdx.x > 0) return;
    const float* A  = WC + (size_t)which * UU * UU;
    const float* Bm = (which == 0) ? WBr : (which == 1) ? (WBr + UU * UU) : Wout;
    float* C = (which == 0) ? g_W1 + UU * UU : (which == 1) ? g_W2 + UU * UU : g_Wo;
    const int N = (which == 2) ? PP : UU;
    __shared__ float As_[32][33], Bs_[32][33];
    const int tx = threadIdx.x, ty = threadIdx.y;
    const int row = blockIdx.y * 32 + ty;
    const int col = blockIdx.x * 32 + tx;
    float s = 0.f;
    for (int k0 = 0; k0 < UU; k0 += 32) {
        As_[ty][tx] = A[(size_t)row * UU + k0 + tx];
        Bs_[ty][tx] = (col < N) ? Bm[(size_t)(k0 + ty) * N + col] : 0.f;
        __syncthreads();
#pragma unroll
        for (int kk = 0; kk < 32; kk++) s = fmaf(As_[ty][kk], Bs_[kk][tx], s);
        __syncthreads();
    }
    if (col < N) C[(size_t)row * N + col] = s;
}

__global__ void make_biases(const float* __restrict__ bA, const float* __restrict__ bB0,
                            const float* __restrict__ bBr, const float* __restrict__ bC,
                            const float* __restrict__ WBr, const float* __restrict__ Wout,
                            const float* __restrict__ bout) {
    const int j = threadIdx.x;
    if (j < UU) {
        g_c0[j] = bA[j] + bB0[j];
        float s1 = 0.f, s2 = 0.f;
        for (int k = 0; k < UU; k++) {
            s1 = fmaf(bC[k], WBr[(size_t)k * UU + j], s1);
            s2 = fmaf(bC[UU + k], WBr[(size_t)UU * UU + (size_t)k * UU + j], s2);
        }
        g_c1[j] = bA[UU + j] + bBr[j] + s1;
        g_c2[j] = bA[2 * UU + j] + bBr[UU + j] + s2;
    }
    if (j < PP) {
        float s = 0.f;
        for (int k = 0; k < UU; k++) s = fmaf(bC[2 * UU + k], Wout[(size_t)k * PP + j], s);
        g_co[j] = bout[j] + s;
    }
}

// ---------------- entry: launches #4,#5,#6 are all rnn_run segments --------
extern "C" void kernel_launch(void* const* d_in, const int* in_sizes, int n_in,
                              void* d_out, int out_size) {
    const float* x    = (const float*)d_in[0];
    const float* WA   = (const float*)d_in[1];
    const float* bA   = (const float*)d_in[2];
    const float* WB0  = (const float*)d_in[3];
    const float* bB0  = (const float*)d_in[4];
    const float* WBr  = (const float*)d_in[5];
    const float* bBr  = (const float*)d_in[6];
    const float* WC   = (const float*)d_in[7];
    const float* bC   = (const float*)d_in[8];
    const float* Wout = (const float*)d_in[9];
    const float* bout = (const float*)d_in[10];
    float* out = (float*)d_out;

    pack_init<<<256, 256>>>(WA, WB0);                                   // #1
    gemm_pre_all<<<dim3(16, 16, 3), dim3(32, 32)>>>(WC, WBr, Wout);     // #2
    make_biases<<<1, 512>>>(bA, bB0, bBr, bC, WBr, Wout, bout);         // #3
    rnn_run<<<NCTA, NTHR>>>(x, out, 0, 171);                            // #4
    rnn_run<<<NCTA, NTHR>>>(x, out, 171, 342);                          // #5
    rnn_run<<<NCTA, NTHR>>>(x, out, 342, 512);                          // #6
}